// round 14
// baseline (speedup 1.0000x reference)
#include <cuda_runtime.h>
#include <cuda_fp16.h>

#define NN 100000
#define NE 1600000
#define SCAN_BLK ((NN + 1023) / 1024)   // 98

// ---------------- scratch (static device allocations only) ----------------
__device__ __align__(16) __half g_T[NN * 128];    // fp16 gather payload (normalized)
__device__ __align__(16) __half g_H1h[NN * 128];  // fp16 layer-1 activation
__device__ __align__(16) __half g_H2h[NN * 128];  // fp16 layer-2 activation
__device__ float g_norm_out[NN];
__device__ float g_norm_in[NN];
__device__ int   g_deg_out[NN];
__device__ int   g_deg_in[NN];
__device__ int   g_rowptr[NN + 1];
__device__ int   g_fill[NN];
__device__ int   g_col[NE];
__device__ int   g_bsum[SCAN_BLK];
__device__ int   g_is64;

// ---------------- index dtype detection ----------------
__global__ void detect_kernel(const int* __restrict__ src_raw) {
    if (threadIdx.x == 0 && blockIdx.x == 0) {
        int is64 = 1;
        for (int i = 0; i < 64; ++i)
            if (src_raw[2 * i + 1] != 0) { is64 = 0; break; }
        g_is64 = is64;
    }
}

__device__ __forceinline__ int load_idx(const void* p, int e, int is64) {
    if (is64) return (int)((const long long*)p)[e];
    return ((const int*)p)[e];
}

// ---------------- graph preprocessing ----------------
__global__ void initA_kernel() {
    int i = blockIdx.x * blockDim.x + threadIdx.x;
    if (i < NN) g_deg_out[i] = 0;
}

__global__ void initB_kernel() {
    int i = blockIdx.x * blockDim.x + threadIdx.x;
    if (i < NN) { g_deg_in[i] = 0; g_fill[i] = 0; }
}

__global__ void countA_kernel(const void* __restrict__ src) {
    int e = blockIdx.x * blockDim.x + threadIdx.x;
    int is64 = g_is64;
    if (e < NE) atomicAdd(&g_deg_out[load_idx(src, e, is64)], 1);
}

__global__ void countB_kernel(const void* __restrict__ dst) {
    int e = blockIdx.x * blockDim.x + threadIdx.x;
    int is64 = g_is64;
    if (e < NE) atomicAdd(&g_deg_in[load_idx(dst, e, is64)], 1);
}

__global__ void normout_kernel() {
    int i = blockIdx.x * blockDim.x + threadIdx.x;
    if (i < NN) g_norm_out[i] = rsqrtf((float)max(g_deg_out[i], 1));
}

__global__ __launch_bounds__(1024) void scanA_kernel() {
    __shared__ int wsum[32];
    int i = blockIdx.x * 1024 + threadIdx.x;
    int lane = threadIdx.x & 31, wid = threadIdx.x >> 5;
    int v = (i < NN) ? g_deg_in[i] : 0;
    int x = v;
    #pragma unroll
    for (int o = 1; o < 32; o <<= 1) {
        int t = __shfl_up_sync(0xffffffffu, x, o);
        if (lane >= o) x += t;
    }
    if (lane == 31) wsum[wid] = x;
    __syncthreads();
    if (wid == 0) {
        int y = wsum[lane];
        #pragma unroll
        for (int o = 1; o < 32; o <<= 1) {
            int t = __shfl_up_sync(0xffffffffu, y, o);
            if (lane >= o) y += t;
        }
        wsum[lane] = y;
    }
    __syncthreads();
    int excl = x - v + (wid > 0 ? wsum[wid - 1] : 0);
    if (i < NN) g_rowptr[i] = excl;
    if (threadIdx.x == 1023) g_bsum[blockIdx.x] = excl + v;
}

__global__ void scanB_kernel() {
    if (threadIdx.x == 0) {
        int s = 0;
        for (int b = 0; b < SCAN_BLK; ++b) {
            int t = g_bsum[b];
            g_bsum[b] = s;
            s += t;
        }
        g_rowptr[NN] = s;
    }
}

__global__ void scanC_kernel() {
    int i = blockIdx.x * blockDim.x + threadIdx.x;
    if (i < NN) {
        g_rowptr[i] += g_bsum[i >> 10];
        g_norm_in[i] = rsqrtf((float)max(g_deg_in[i], 1));
    }
}

__global__ void fill_kernel(const void* __restrict__ src,
                            const void* __restrict__ dst) {
    int e = blockIdx.x * blockDim.x + threadIdx.x;
    int is64 = g_is64;
    if (e < NE) {
        int d = load_idx(dst, e, is64);
        int p = g_rowptr[d] + atomicAdd(&g_fill[d], 1);
        g_col[p] = load_idx(src, e, is64);
    }
}

// ---------------- fp16 MMA helper ----------------
__device__ __forceinline__ void mma_f16(float* c, const unsigned* a, const unsigned* b) {
    asm volatile(
        "mma.sync.aligned.m16n8k16.row.col.f32.f16.f16.f32 "
        "{%0,%1,%2,%3}, {%4,%5,%6,%7}, {%8,%9}, {%0,%1,%2,%3};\n"
        : "+f"(c[0]), "+f"(c[1]), "+f"(c[2]), "+f"(c[3])
        : "r"(a[0]), "r"(a[1]), "r"(a[2]), "r"(a[3]), "r"(b[0]), "r"(b[1]));
}

// ---------------- HMMA GEMM: g_T(half) = (A @ W) * norm_out[:,None] -----------
template <int BN, int SRCSEL>
__global__ __launch_bounds__(256) void gemm_hmma_kernel(const float* __restrict__ Xext,
                                                        const float* __restrict__ W) {
    constexpr int BK = 32, LD = 40;
    constexpr int WARPS_N = BN / 32;
    constexpr int WM = 128 / (8 / WARPS_N);
    constexpr int MFR = WM / 16;
    constexpr int NFR = 4;

    __shared__ __align__(16) __half As[128][LD];
    __shared__ __align__(16) __half Bs[BN][LD];

    const int tid = threadIdx.x;
    const int w = tid >> 5, lane = tid & 31;
    const int gid = lane >> 2, tig = lane & 3;
    const int warp_n = (w % WARPS_N) * 32;
    const int warp_m = (w / WARPS_N) * WM;
    const int m0 = blockIdx.x * 128;

    float acc[MFR][NFR][4];
    #pragma unroll
    for (int a = 0; a < MFR; ++a)
        #pragma unroll
        for (int b = 0; b < NFR; ++b)
            #pragma unroll
            for (int c = 0; c < 4; ++c) acc[a][b][c] = 0.f;

    for (int kc = 0; kc < 128; kc += BK) {
        #pragma unroll
        for (int l = 0; l < 2; ++l) {
            int lin = tid + l * 256;
            int row = lin >> 2;
            int cq  = (lin & 3) * 8;
            int gr  = m0 + row;
            __half2 h[4];
            if (gr < NN) {
                if (SRCSEL == 0) {
                    float4 v1 = *(const float4*)(Xext + gr * 128 + kc + cq);
                    float4 v2 = *(const float4*)(Xext + gr * 128 + kc + cq + 4);
                    h[0] = __floats2half2_rn(v1.x, v1.y);
                    h[1] = __floats2half2_rn(v1.z, v1.w);
                    h[2] = __floats2half2_rn(v2.x, v2.y);
                    h[3] = __floats2half2_rn(v2.z, v2.w);
                } else if (SRCSEL == 1) {
                    uint4 u = *(const uint4*)(g_H1h + gr * 128 + kc + cq);
                    h[0] = *(__half2*)&u.x; h[1] = *(__half2*)&u.y;
                    h[2] = *(__half2*)&u.z; h[3] = *(__half2*)&u.w;
                } else {
                    uint4 u1 = *(const uint4*)(g_H1h + gr * 128 + kc + cq);
                    uint4 u2 = *(const uint4*)(g_H2h + gr * 128 + kc + cq);
                    const unsigned* a1 = &u1.x;
                    const unsigned* a2 = &u2.x;
                    #pragma unroll
                    for (int q = 0; q < 4; ++q) {
                        float2 p = __half22float2(*(__half2*)&a1[q]);
                        float2 r = __half22float2(*(__half2*)&a2[q]);
                        h[q] = __floats2half2_rn(0.9f * p.x + 0.1f * r.x,
                                                 0.9f * p.y + 0.1f * r.y);
                    }
                }
            } else {
                h[0] = h[1] = h[2] = h[3] = __floats2half2_rn(0.f, 0.f);
            }
            uint2 w0, w1;
            w0.x = *(unsigned*)&h[0]; w0.y = *(unsigned*)&h[1];
            w1.x = *(unsigned*)&h[2]; w1.y = *(unsigned*)&h[3];
            *(uint2*)&As[row][cq]     = w0;
            *(uint2*)&As[row][cq + 4] = w1;
        }
        #pragma unroll
        for (int l = 0; l < BN / 32; ++l) {
            int lin = tid + l * 256;
            int k  = lin / (BN / 4);
            int nq = (lin % (BN / 4)) * 4;
            float4 v = *(const float4*)(W + (kc + k) * BN + nq);
            Bs[nq + 0][k] = __float2half_rn(v.x);
            Bs[nq + 1][k] = __float2half_rn(v.y);
            Bs[nq + 2][k] = __float2half_rn(v.z);
            Bs[nq + 3][k] = __float2half_rn(v.w);
        }
        __syncthreads();

        #pragma unroll
        for (int ks = 0; ks < BK; ks += 16) {
            unsigned bh[NFR][2];
            #pragma unroll
            for (int nf = 0; nf < NFR; ++nf) {
                int n = warp_n + nf * 8 + gid;
                bh[nf][0] = *(const unsigned*)&Bs[n][ks + 2 * tig];
                bh[nf][1] = *(const unsigned*)&Bs[n][ks + 2 * tig + 8];
            }
            #pragma unroll
            for (int mf = 0; mf < MFR; ++mf) {
                int m = warp_m + mf * 16;
                unsigned ah[4];
                ah[0] = *(const unsigned*)&As[m + gid][ks + 2 * tig];
                ah[1] = *(const unsigned*)&As[m + gid + 8][ks + 2 * tig];
                ah[2] = *(const unsigned*)&As[m + gid][ks + 2 * tig + 8];
                ah[3] = *(const unsigned*)&As[m + gid + 8][ks + 2 * tig + 8];
                #pragma unroll
                for (int nf = 0; nf < NFR; ++nf)
                    mma_f16(acc[mf][nf], ah, bh[nf]);
            }
        }
        __syncthreads();
    }

    #pragma unroll
    for (int mf = 0; mf < MFR; ++mf) {
        int r0 = m0 + warp_m + mf * 16 + gid;
        int r1 = r0 + 8;
        float no0 = (r0 < NN) ? g_norm_out[r0] : 0.f;
        float no1 = (r1 < NN) ? g_norm_out[r1] : 0.f;
        #pragma unroll
        for (int nf = 0; nf < NFR; ++nf) {
            int col = warp_n + nf * 8 + 2 * tig;
            if (r0 < NN)
                *(__half2*)&g_T[r0 * BN + col] =
                    __floats2half2_rn(acc[mf][nf][0] * no0, acc[mf][nf][1] * no0);
            if (r1 < NN)
                *(__half2*)&g_T[r1 * BN + col] =
                    __floats2half2_rn(acc[mf][nf][2] * no1, acc[mf][nf][3] * no1);
        }
    }
}

// -------- aggregation, F=128: TWO warps per node (64 feats each) --------
// Same edge order per feature as before -> bit-identical accumulation.
template <bool RELU, int OUTSEL>   // OUTSEL: 0=g_H1h, 1=g_H2h
__global__ __launch_bounds__(256) void agg128_kernel(const float* __restrict__ bias) {
    int gw = (blockIdx.x * 256 + threadIdx.x) >> 5;
    int w = gw >> 1;                 // node
    int half = gw & 1;               // feature half
    int lane = threadIdx.x & 31;
    if (w >= NN) return;
    int s0 = g_rowptr[w];
    int s1 = g_rowptr[w + 1];
    float ni = g_norm_in[w];
    const __half* T = g_T;
    const int off = half * 64 + lane * 2;   // 2 halves (4 B) per lane

    float2 a = make_float2(0.f, 0.f);
    int e = s0;
    for (; e + 4 <= s1; e += 4) {
        int c0 = g_col[e + 0], c1 = g_col[e + 1];
        int c2 = g_col[e + 2], c3 = g_col[e + 3];
        unsigned u0 = *(const unsigned*)(T + c0 * 128 + off);
        unsigned u1 = *(const unsigned*)(T + c1 * 128 + off);
        unsigned u2 = *(const unsigned*)(T + c2 * 128 + off);
        unsigned u3 = *(const unsigned*)(T + c3 * 128 + off);
        float2 p;
        p = __half22float2(*(__half2*)&u0); a.x += p.x; a.y += p.y;
        p = __half22float2(*(__half2*)&u1); a.x += p.x; a.y += p.y;
        p = __half22float2(*(__half2*)&u2); a.x += p.x; a.y += p.y;
        p = __half22float2(*(__half2*)&u3); a.x += p.x; a.y += p.y;
    }
    for (; e < s1; ++e) {
        int c = g_col[e];
        unsigned u = *(const unsigned*)(T + c * 128 + off);
        float2 p = __half22float2(*(__half2*)&u);
        a.x += p.x; a.y += p.y;
    }
    float2 b = *(const float2*)(bias + off);
    float2 r = make_float2(fmaf(a.x, ni, b.x), fmaf(a.y, ni, b.y));
    if (RELU) { r.x = fmaxf(r.x, 0.f); r.y = fmaxf(r.y, 0.f); }
    __half* dstp = (OUTSEL == 0) ? g_H1h : g_H2h;
    __half2 h = __floats2half2_rn(r.x, r.y);
    *(unsigned*)(dstp + w * 128 + off) = *(unsigned*)&h;
}

// -------- aggregation, F=64 (layer 3): one warp per node, fp32 out --------
__global__ __launch_bounds__(256) void agg64_kernel(const float* __restrict__ bias,
                                                    float* __restrict__ Oext) {
    int w = (blockIdx.x * 256 + threadIdx.x) >> 5;
    int lane = threadIdx.x & 31;
    if (w >= NN) return;
    int s0 = g_rowptr[w];
    int s1 = g_rowptr[w + 1];
    float ni = g_norm_in[w];
    const __half* T = g_T;
    const int off = lane * 2;

    float2 a = make_float2(0.f, 0.f);
    int e = s0;
    for (; e + 4 <= s1; e += 4) {
        int c0 = g_col[e + 0], c1 = g_col[e + 1];
        int c2 = g_col[e + 2], c3 = g_col[e + 3];
        unsigned u0 = *(const unsigned*)(T + c0 * 64 + off);
        unsigned u1 = *(const unsigned*)(T + c1 * 64 + off);
        unsigned u2 = *(const unsigned*)(T + c2 * 64 + off);
        unsigned u3 = *(const unsigned*)(T + c3 * 64 + off);
        float2 p;
        p = __half22float2(*(__half2*)&u0); a.x += p.x; a.y += p.y;
        p = __half22float2(*(__half2*)&u1); a.x += p.x; a.y += p.y;
        p = __half22float2(*(__half2*)&u2); a.x += p.x; a.y += p.y;
        p = __half22float2(*(__half2*)&u3); a.x += p.x; a.y += p.y;
    }
    for (; e < s1; ++e) {
        int c = g_col[e];
        unsigned u = *(const unsigned*)(T + c * 64 + off);
        float2 p = __half22float2(*(__half2*)&u);
        a.x += p.x; a.y += p.y;
    }
    float2 b = *(const float2*)(bias + off);
    float2 r = make_float2(fmaf(a.x, ni, b.x), fmaf(a.y, ni, b.y));
    *(float2*)(Oext + w * 64 + off) = r;
}

// ---------------- driver (R9 topology) ----------------
extern "C" void kernel_launch(void* const* d_in, const int* in_sizes, int n_in,
                              void* d_out, int out_size) {
    const float* x   = (const float*)d_in[0];
    const void*  src = d_in[1];
    const void*  dst = d_in[2];
    const float* W1 = (const float*)d_in[3];
    const float* b1 = (const float*)d_in[4];
    const float* W2 = (const float*)d_in[5];
    const float* b2 = (const float*)d_in[6];
    const float* W3 = (const float*)d_in[7];
    const float* b3 = (const float*)d_in[8];
    float* out = (float*)d_out;

    const int NB_N  = (NN + 255) / 256;
    const int NB_E  = (NE + 255) / 256;
    const int NB_G  = (NN + 127) / 128;
    const int NB_A  = (NN * 32 + 255) / 256;        // 1 warp/node (layer 3)
    const int NB_A2 = (NN * 64 + 255) / 256;        // 2 warps/node (layers 1-2)

    static cudaStream_t s1 = nullptr;
    static cudaEvent_t evFork = nullptr, evJoin = nullptr;
    if (s1 == nullptr) {
        cudaStreamCreateWithFlags(&s1, cudaStreamNonBlocking);
        cudaEventCreateWithFlags(&evFork, cudaEventDisableTiming);
        cudaEventCreateWithFlags(&evJoin, cudaEventDisableTiming);
    }

    // --- common root: index dtype detection ---
    detect_kernel<<<1, 32>>>((const int*)src);
    cudaEventRecord(evFork, 0);

    // --- stream s1: dst-side chain (CSR build) ---
    cudaStreamWaitEvent(s1, evFork, 0);
    initB_kernel<<<NB_N, 256, 0, s1>>>();
    countB_kernel<<<NB_E, 256, 0, s1>>>(dst);
    scanA_kernel<<<SCAN_BLK, 1024, 0, s1>>>();
    scanB_kernel<<<1, 32, 0, s1>>>();
    scanC_kernel<<<NB_N, 256, 0, s1>>>();
    fill_kernel<<<NB_E, 256, 0, s1>>>(src, dst);
    cudaEventRecord(evJoin, s1);

    // --- default stream: src-side chain + layer-1 GEMM (overlaps CSR build) ---
    initA_kernel<<<NB_N, 256>>>();
    countA_kernel<<<NB_E, 256>>>(src);
    normout_kernel<<<NB_N, 256>>>();
    gemm_hmma_kernel<128, 0><<<NB_G, 256>>>(x, W1);

    // --- join: aggregation needs CSR + norms ---
    cudaStreamWaitEvent(0, evJoin, 0);
    agg128_kernel<true, 0><<<NB_A2, 256>>>(b1);

    // layer 2
    gemm_hmma_kernel<128, 1><<<NB_G, 256>>>(nullptr, W2);
    agg128_kernel<true, 1><<<NB_A2, 256>>>(b2);

    // layer 3
    gemm_hmma_kernel<64, 2><<<NB_G, 256>>>(nullptr, W3);
    agg64_kernel<<<NB_A, 256>>>(b3, out);
}

// round 15
// speedup vs baseline: 1.0915x; 1.0915x over previous
#include <cuda_runtime.h>
#include <cuda_fp16.h>

#define NN 100000
#define NE 1600000
#define SCAN_BLK ((NN + 1023) / 1024)   // 98
#define SPLIT_NODE 50048                 // 391 GEMM tiles * 128 = 6256 agg blocks * 8

// ---------------- scratch (static device allocations only) ----------------
__device__ __align__(16) __half g_T [NN * 128];   // payload buffer A (layers 1,3)
__device__ __align__(16) __half g_T2[NN * 128];   // payload buffer B (layer 2)
__device__ __align__(16) __half g_H1h[NN * 128];
__device__ __align__(16) __half g_H2h[NN * 128];
__device__ float g_norm_out[NN];
__device__ float g_norm_in[NN];
__device__ int   g_deg_out[NN];
__device__ int   g_deg_in[NN];
__device__ int   g_rowptr[NN + 1];
__device__ int   g_fill[NN];
__device__ int   g_col[NE];
__device__ int   g_bsum[SCAN_BLK];
__device__ int   g_is64;

// ---------------- index dtype detection ----------------
__global__ void detect_kernel(const int* __restrict__ src_raw) {
    if (threadIdx.x == 0 && blockIdx.x == 0) {
        int is64 = 1;
        for (int i = 0; i < 64; ++i)
            if (src_raw[2 * i + 1] != 0) { is64 = 0; break; }
        g_is64 = is64;
    }
}

__device__ __forceinline__ int load_idx(const void* p, int e, int is64) {
    if (is64) return (int)((const long long*)p)[e];
    return ((const int*)p)[e];
}

// ---------------- graph preprocessing ----------------
__global__ void initA_kernel() {
    int i = blockIdx.x * blockDim.x + threadIdx.x;
    if (i < NN) g_deg_out[i] = 0;
}

__global__ void initB_kernel() {
    int i = blockIdx.x * blockDim.x + threadIdx.x;
    if (i < NN) { g_deg_in[i] = 0; g_fill[i] = 0; }
}

__global__ void countA_kernel(const void* __restrict__ src) {
    int e = blockIdx.x * blockDim.x + threadIdx.x;
    int is64 = g_is64;
    if (e < NE) atomicAdd(&g_deg_out[load_idx(src, e, is64)], 1);
}

__global__ void countB_kernel(const void* __restrict__ dst) {
    int e = blockIdx.x * blockDim.x + threadIdx.x;
    int is64 = g_is64;
    if (e < NE) atomicAdd(&g_deg_in[load_idx(dst, e, is64)], 1);
}

__global__ void normout_kernel() {
    int i = blockIdx.x * blockDim.x + threadIdx.x;
    if (i < NN) g_norm_out[i] = rsqrtf((float)max(g_deg_out[i], 1));
}

__global__ __launch_bounds__(1024) void scanA_kernel() {
    __shared__ int wsum[32];
    int i = blockIdx.x * 1024 + threadIdx.x;
    int lane = threadIdx.x & 31, wid = threadIdx.x >> 5;
    int v = (i < NN) ? g_deg_in[i] : 0;
    int x = v;
    #pragma unroll
    for (int o = 1; o < 32; o <<= 1) {
        int t = __shfl_up_sync(0xffffffffu, x, o);
        if (lane >= o) x += t;
    }
    if (lane == 31) wsum[wid] = x;
    __syncthreads();
    if (wid == 0) {
        int y = wsum[lane];
        #pragma unroll
        for (int o = 1; o < 32; o <<= 1) {
            int t = __shfl_up_sync(0xffffffffu, y, o);
            if (lane >= o) y += t;
        }
        wsum[lane] = y;
    }
    __syncthreads();
    int excl = x - v + (wid > 0 ? wsum[wid - 1] : 0);
    if (i < NN) g_rowptr[i] = excl;
    if (threadIdx.x == 1023) g_bsum[blockIdx.x] = excl + v;
}

__global__ void scanB_kernel() {
    if (threadIdx.x == 0) {
        int s = 0;
        for (int b = 0; b < SCAN_BLK; ++b) {
            int t = g_bsum[b];
            g_bsum[b] = s;
            s += t;
        }
        g_rowptr[NN] = s;
    }
}

__global__ void scanC_kernel() {
    int i = blockIdx.x * blockDim.x + threadIdx.x;
    if (i < NN) {
        g_rowptr[i] += g_bsum[i >> 10];
        g_norm_in[i] = rsqrtf((float)max(g_deg_in[i], 1));
    }
}

__global__ void fill_kernel(const void* __restrict__ src,
                            const void* __restrict__ dst) {
    int e = blockIdx.x * blockDim.x + threadIdx.x;
    int is64 = g_is64;
    if (e < NE) {
        int d = load_idx(dst, e, is64);
        int p = g_rowptr[d] + atomicAdd(&g_fill[d], 1);
        g_col[p] = load_idx(src, e, is64);
    }
}

// ---------------- fp16 MMA helper ----------------
__device__ __forceinline__ void mma_f16(float* c, const unsigned* a, const unsigned* b) {
    asm volatile(
        "mma.sync.aligned.m16n8k16.row.col.f32.f16.f16.f32 "
        "{%0,%1,%2,%3}, {%4,%5,%6,%7}, {%8,%9}, {%0,%1,%2,%3};\n"
        : "+f"(c[0]), "+f"(c[1]), "+f"(c[2]), "+f"(c[3])
        : "r"(a[0]), "r"(a[1]), "r"(a[2]), "r"(a[3]), "r"(b[0]), "r"(b[1]));
}

// ---------------- HMMA GEMM: Tout = (A @ W) * norm_out[:,None] -----------
// TSEL: 0 -> g_T, 1 -> g_T2. tile0: starting 128-row tile index.
template <int BN, int SRCSEL, int TSEL>
__global__ __launch_bounds__(256) void gemm_hmma_kernel(const float* __restrict__ Xext,
                                                        const float* __restrict__ W,
                                                        int tile0) {
    constexpr int BK = 32, LD = 40;
    constexpr int WARPS_N = BN / 32;
    constexpr int WM = 128 / (8 / WARPS_N);
    constexpr int MFR = WM / 16;
    constexpr int NFR = 4;

    __shared__ __align__(16) __half As[128][LD];
    __shared__ __align__(16) __half Bs[BN][LD];

    const int tid = threadIdx.x;
    const int w = tid >> 5, lane = tid & 31;
    const int gid = lane >> 2, tig = lane & 3;
    const int warp_n = (w % WARPS_N) * 32;
    const int warp_m = (w / WARPS_N) * WM;
    const int m0 = (blockIdx.x + tile0) * 128;
    __half* Tout = (TSEL == 0) ? g_T : g_T2;

    float acc[MFR][NFR][4];
    #pragma unroll
    for (int a = 0; a < MFR; ++a)
        #pragma unroll
        for (int b = 0; b < NFR; ++b)
            #pragma unroll
            for (int c = 0; c < 4; ++c) acc[a][b][c] = 0.f;

    for (int kc = 0; kc < 128; kc += BK) {
        #pragma unroll
        for (int l = 0; l < 2; ++l) {
            int lin = tid + l * 256;
            int row = lin >> 2;
            int cq  = (lin & 3) * 8;
            int gr  = m0 + row;
            __half2 h[4];
            if (gr < NN) {
                if (SRCSEL == 0) {
                    float4 v1 = *(const float4*)(Xext + gr * 128 + kc + cq);
                    float4 v2 = *(const float4*)(Xext + gr * 128 + kc + cq + 4);
                    h[0] = __floats2half2_rn(v1.x, v1.y);
                    h[1] = __floats2half2_rn(v1.z, v1.w);
                    h[2] = __floats2half2_rn(v2.x, v2.y);
                    h[3] = __floats2half2_rn(v2.z, v2.w);
                } else if (SRCSEL == 1) {
                    uint4 u = *(const uint4*)(g_H1h + gr * 128 + kc + cq);
                    h[0] = *(__half2*)&u.x; h[1] = *(__half2*)&u.y;
                    h[2] = *(__half2*)&u.z; h[3] = *(__half2*)&u.w;
                } else {
                    uint4 u1 = *(const uint4*)(g_H1h + gr * 128 + kc + cq);
                    uint4 u2 = *(const uint4*)(g_H2h + gr * 128 + kc + cq);
                    const unsigned* a1 = &u1.x;
                    const unsigned* a2 = &u2.x;
                    #pragma unroll
                    for (int q = 0; q < 4; ++q) {
                        float2 p = __half22float2(*(__half2*)&a1[q]);
                        float2 r = __half22float2(*(__half2*)&a2[q]);
                        h[q] = __floats2half2_rn(0.9f * p.x + 0.1f * r.x,
                                                 0.9f * p.y + 0.1f * r.y);
                    }
                }
            } else {
                h[0] = h[1] = h[2] = h[3] = __floats2half2_rn(0.f, 0.f);
            }
            uint2 w0, w1;
            w0.x = *(unsigned*)&h[0]; w0.y = *(unsigned*)&h[1];
            w1.x = *(unsigned*)&h[2]; w1.y = *(unsigned*)&h[3];
            *(uint2*)&As[row][cq]     = w0;
            *(uint2*)&As[row][cq + 4] = w1;
        }
        #pragma unroll
        for (int l = 0; l < BN / 32; ++l) {
            int lin = tid + l * 256;
            int k  = lin / (BN / 4);
            int nq = (lin % (BN / 4)) * 4;
            float4 v = *(const float4*)(W + (kc + k) * BN + nq);
            Bs[nq + 0][k] = __float2half_rn(v.x);
            Bs[nq + 1][k] = __float2half_rn(v.y);
            Bs[nq + 2][k] = __float2half_rn(v.z);
            Bs[nq + 3][k] = __float2half_rn(v.w);
        }
        __syncthreads();

        #pragma unroll
        for (int ks = 0; ks < BK; ks += 16) {
            unsigned bh[NFR][2];
            #pragma unroll
            for (int nf = 0; nf < NFR; ++nf) {
                int n = warp_n + nf * 8 + gid;
                bh[nf][0] = *(const unsigned*)&Bs[n][ks + 2 * tig];
                bh[nf][1] = *(const unsigned*)&Bs[n][ks + 2 * tig + 8];
            }
            #pragma unroll
            for (int mf = 0; mf < MFR; ++mf) {
                int m = warp_m + mf * 16;
                unsigned ah[4];
                ah[0] = *(const unsigned*)&As[m + gid][ks + 2 * tig];
                ah[1] = *(const unsigned*)&As[m + gid + 8][ks + 2 * tig];
                ah[2] = *(const unsigned*)&As[m + gid][ks + 2 * tig + 8];
                ah[3] = *(const unsigned*)&As[m + gid + 8][ks + 2 * tig + 8];
                #pragma unroll
                for (int nf = 0; nf < NFR; ++nf)
                    mma_f16(acc[mf][nf], ah, bh[nf]);
            }
        }
        __syncthreads();
    }

    #pragma unroll
    for (int mf = 0; mf < MFR; ++mf) {
        int r0 = m0 + warp_m + mf * 16 + gid;
        int r1 = r0 + 8;
        float no0 = (r0 < NN) ? g_norm_out[r0] : 0.f;
        float no1 = (r1 < NN) ? g_norm_out[r1] : 0.f;
        #pragma unroll
        for (int nf = 0; nf < NFR; ++nf) {
            int col = warp_n + nf * 8 + 2 * tig;
            if (r0 < NN)
                *(__half2*)&Tout[r0 * BN + col] =
                    __floats2half2_rn(acc[mf][nf][0] * no0, acc[mf][nf][1] * no0);
            if (r1 < NN)
                *(__half2*)&Tout[r1 * BN + col] =
                    __floats2half2_rn(acc[mf][nf][2] * no1, acc[mf][nf][3] * no1);
        }
    }
}

// -------- aggregation, F=128 (R13 shape: 1 warp/node, uint2 loads) --------
// TSEL payload select; node0: starting node offset.
template <bool RELU, int OUTSEL, int TSEL>   // OUTSEL: 0=g_H1h, 1=g_H2h
__global__ __launch_bounds__(256) void agg128_kernel(const float* __restrict__ bias,
                                                     int node0) {
    int w = ((blockIdx.x * 256 + threadIdx.x) >> 5) + node0;
    int lane = threadIdx.x & 31;
    if (w >= NN) return;
    int s0 = g_rowptr[w];
    int s1 = g_rowptr[w + 1];
    float ni = g_norm_in[w];
    const __half* T = (TSEL == 0) ? g_T : g_T2;
    const int off = lane * 4;

    float4 a = make_float4(0.f, 0.f, 0.f, 0.f);
    int e = s0;
    for (; e + 4 <= s1; e += 4) {
        int c0 = g_col[e + 0], c1 = g_col[e + 1];
        int c2 = g_col[e + 2], c3 = g_col[e + 3];
        uint2 u0 = *(const uint2*)(T + c0 * 128 + off);
        uint2 u1 = *(const uint2*)(T + c1 * 128 + off);
        uint2 u2 = *(const uint2*)(T + c2 * 128 + off);
        uint2 u3 = *(const uint2*)(T + c3 * 128 + off);
        float2 p, q;
        p = __half22float2(*(__half2*)&u0.x); q = __half22float2(*(__half2*)&u0.y);
        a.x += p.x; a.y += p.y; a.z += q.x; a.w += q.y;
        p = __half22float2(*(__half2*)&u1.x); q = __half22float2(*(__half2*)&u1.y);
        a.x += p.x; a.y += p.y; a.z += q.x; a.w += q.y;
        p = __half22float2(*(__half2*)&u2.x); q = __half22float2(*(__half2*)&u2.y);
        a.x += p.x; a.y += p.y; a.z += q.x; a.w += q.y;
        p = __half22float2(*(__half2*)&u3.x); q = __half22float2(*(__half2*)&u3.y);
        a.x += p.x; a.y += p.y; a.z += q.x; a.w += q.y;
    }
    for (; e < s1; ++e) {
        int c = g_col[e];
        uint2 u = *(const uint2*)(T + c * 128 + off);
        float2 p = __half22float2(*(__half2*)&u.x);
        float2 q = __half22float2(*(__half2*)&u.y);
        a.x += p.x; a.y += p.y; a.z += q.x; a.w += q.y;
    }
    float4 b = *(const float4*)(bias + off);
    float4 r = make_float4(fmaf(a.x, ni, b.x), fmaf(a.y, ni, b.y),
                           fmaf(a.z, ni, b.z), fmaf(a.w, ni, b.w));
    if (RELU) {
        r.x = fmaxf(r.x, 0.f); r.y = fmaxf(r.y, 0.f);
        r.z = fmaxf(r.z, 0.f); r.w = fmaxf(r.w, 0.f);
    }
    __half* dstp = (OUTSEL == 0) ? g_H1h : g_H2h;
    uint2 hw;
    __half2 h0 = __floats2half2_rn(r.x, r.y);
    __half2 h1 = __floats2half2_rn(r.z, r.w);
    hw.x = *(unsigned*)&h0; hw.y = *(unsigned*)&h1;
    *(uint2*)(dstp + w * 128 + off) = hw;
}

// -------- aggregation, F=64 (layer 3): one warp per node, fp32 out --------
__global__ __launch_bounds__(256) void agg64_kernel(const float* __restrict__ bias,
                                                    float* __restrict__ Oext) {
    int w = (blockIdx.x * 256 + threadIdx.x) >> 5;
    int lane = threadIdx.x & 31;
    if (w >= NN) return;
    int s0 = g_rowptr[w];
    int s1 = g_rowptr[w + 1];
    float ni = g_norm_in[w];
    const __half* T = g_T;
    const int off = lane * 2;

    float2 a = make_float2(0.f, 0.f);
    int e = s0;
    for (; e + 4 <= s1; e += 4) {
        int c0 = g_col[e + 0], c1 = g_col[e + 1];
        int c2 = g_col[e + 2], c3 = g_col[e + 3];
        unsigned u0 = *(const unsigned*)(T + c0 * 64 + off);
        unsigned u1 = *(const unsigned*)(T + c1 * 64 + off);
        unsigned u2 = *(const unsigned*)(T + c2 * 64 + off);
        unsigned u3 = *(const unsigned*)(T + c3 * 64 + off);
        float2 p;
        p = __half22float2(*(__half2*)&u0); a.x += p.x; a.y += p.y;
        p = __half22float2(*(__half2*)&u1); a.x += p.x; a.y += p.y;
        p = __half22float2(*(__half2*)&u2); a.x += p.x; a.y += p.y;
        p = __half22float2(*(__half2*)&u3); a.x += p.x; a.y += p.y;
    }
    for (; e < s1; ++e) {
        int c = g_col[e];
        unsigned u = *(const unsigned*)(T + c * 64 + off);
        float2 p = __half22float2(*(__half2*)&u);
        a.x += p.x; a.y += p.y;
    }
    float2 b = *(const float2*)(bias + off);
    float2 r = make_float2(fmaf(a.x, ni, b.x), fmaf(a.y, ni, b.y));
    *(float2*)(Oext + w * 64 + off) = r;
}

// ---------------- driver ----------------
extern "C" void kernel_launch(void* const* d_in, const int* in_sizes, int n_in,
                              void* d_out, int out_size) {
    const float* x   = (const float*)d_in[0];
    const void*  src = d_in[1];
    const void*  dst = d_in[2];
    const float* W1 = (const float*)d_in[3];
    const float* b1 = (const float*)d_in[4];
    const float* W2 = (const float*)d_in[5];
    const float* b2 = (const float*)d_in[6];
    const float* W3 = (const float*)d_in[7];
    const float* b3 = (const float*)d_in[8];
    float* out = (float*)d_out;

    const int NB_N  = (NN + 255) / 256;
    const int NB_E  = (NE + 255) / 256;
    const int NB_G  = (NN + 127) / 128;            // 782
    const int G_H0  = SPLIT_NODE / 128;            // 391
    const int G_H1  = NB_G - G_H0;                 // 391
    const int NB_A  = (NN * 32 + 255) / 256;       // 12500 (1 warp/node)
    const int A_H0  = SPLIT_NODE / 8;              // 6256 blocks (8 nodes/block)
    const int A_H1  = NB_A - A_H0;                 // 6244

    static cudaStream_t s1 = nullptr;
    static cudaEvent_t evFork = nullptr, evJoin = nullptr;
    static cudaEvent_t eA0 = nullptr, eA1 = nullptr, eG2 = nullptr;
    static cudaEvent_t eB0 = nullptr, eB1 = nullptr, eG3 = nullptr;
    if (s1 == nullptr) {
        cudaStreamCreateWithFlags(&s1, cudaStreamNonBlocking);
        cudaEventCreateWithFlags(&evFork, cudaEventDisableTiming);
        cudaEventCreateWithFlags(&evJoin, cudaEventDisableTiming);
        cudaEventCreateWithFlags(&eA0, cudaEventDisableTiming);
        cudaEventCreateWithFlags(&eA1, cudaEventDisableTiming);
        cudaEventCreateWithFlags(&eG2, cudaEventDisableTiming);
        cudaEventCreateWithFlags(&eB0, cudaEventDisableTiming);
        cudaEventCreateWithFlags(&eB1, cudaEventDisableTiming);
        cudaEventCreateWithFlags(&eG3, cudaEventDisableTiming);
    }

    // --- common root: index dtype detection ---
    detect_kernel<<<1, 32>>>((const int*)src);
    cudaEventRecord(evFork, 0);

    // --- stream s1: dst-side chain (CSR build) ---
    cudaStreamWaitEvent(s1, evFork, 0);
    initB_kernel<<<NB_N, 256, 0, s1>>>();
    countB_kernel<<<NB_E, 256, 0, s1>>>(dst);
    scanA_kernel<<<SCAN_BLK, 1024, 0, s1>>>();
    scanB_kernel<<<1, 32, 0, s1>>>();
    scanC_kernel<<<NB_N, 256, 0, s1>>>();
    fill_kernel<<<NB_E, 256, 0, s1>>>(src, dst);
    cudaEventRecord(evJoin, s1);

    // --- default stream: src-side chain + layer-1 GEMM (overlaps CSR build) ---
    initA_kernel<<<NB_N, 256>>>();
    countA_kernel<<<NB_E, 256>>>(src);
    normout_kernel<<<NB_N, 256>>>();
    gemm_hmma_kernel<128, 0, 0><<<NB_G, 256>>>(x, W1, 0);        // full, -> g_T

    // --- join: aggregation needs CSR + norms ---
    cudaStreamWaitEvent(0, evJoin, 0);

    // --- layer 1 agg (split) overlapped with layer 2 GEMM (split) ---
    agg128_kernel<true, 0, 0><<<A_H0, 256>>>(b1, 0);             // nodes [0, SPLIT)
    cudaEventRecord(eA0, 0);
    agg128_kernel<true, 0, 0><<<A_H1, 256>>>(b1, SPLIT_NODE);    // nodes [SPLIT, NN)
    cudaEventRecord(eA1, 0);
    cudaStreamWaitEvent(s1, eA0, 0);
    gemm_hmma_kernel<128, 1, 1><<<G_H0, 256, 0, s1>>>(nullptr, W2, 0);    // -> g_T2
    cudaStreamWaitEvent(s1, eA1, 0);
    gemm_hmma_kernel<128, 1, 1><<<G_H1, 256, 0, s1>>>(nullptr, W2, G_H0);
    cudaEventRecord(eG2, s1);

    // --- layer 2 agg (split) overlapped with layer 3 GEMM (split) ---
    cudaStreamWaitEvent(0, eG2, 0);
    agg128_kernel<true, 1, 1><<<A_H0, 256>>>(b2, 0);
    cudaEventRecord(eB0, 0);
    agg128_kernel<true, 1, 1><<<A_H1, 256>>>(b2, SPLIT_NODE);
    cudaEventRecord(eB1, 0);
    cudaStreamWaitEvent(s1, eB0, 0);
    gemm_hmma_kernel<64, 2, 0><<<G_H0, 256, 0, s1>>>(nullptr, W3, 0);     // -> g_T
    cudaStreamWaitEvent(s1, eB1, 0);
    gemm_hmma_kernel<64, 2, 0><<<G_H1, 256, 0, s1>>>(nullptr, W3, G_H0);
    cudaEventRecord(eG3, s1);

    // --- layer 3 agg (full) ---
    cudaStreamWaitEvent(0, eG3, 0);
    agg64_kernel<<<NB_A, 256>>>(b3, out);
}

// round 16
// speedup vs baseline: 1.1761x; 1.0775x over previous
#include <cuda_runtime.h>
#include <cuda_fp16.h>

#define NN 100000
#define NE 1600000
#define SCAN_BLK ((NN + 1023) / 1024)   // 98

// ---------------- scratch (static device allocations only) ----------------
__device__ __align__(16) __half g_T[NN * 128];    // fp16 gather payload (normalized)
__device__ __align__(16) __half g_H1h[NN * 128];  // fp16 layer-1 activation
__device__ __align__(16) __half g_H2h[NN * 128];  // fp16 layer-2 activation
__device__ float g_norm_out[NN];
__device__ float g_norm_in[NN];
__device__ int   g_deg_out[NN];
__device__ int   g_deg_in[NN];
__device__ int   g_rowptr[NN + 1];
__device__ int   g_fill[NN];
__device__ int   g_col[NE];
__device__ int   g_bsum[SCAN_BLK];
__device__ int   g_is64;

// ---------------- index dtype detection ----------------
__global__ void detect_kernel(const int* __restrict__ src_raw) {
    if (threadIdx.x == 0 && blockIdx.x == 0) {
        int is64 = 1;
        for (int i = 0; i < 64; ++i)
            if (src_raw[2 * i + 1] != 0) { is64 = 0; break; }
        g_is64 = is64;
    }
}

__device__ __forceinline__ int load_idx(const void* p, int e, int is64) {
    if (is64) return (int)((const long long*)p)[e];
    return ((const int*)p)[e];
}

// ---------------- graph preprocessing ----------------
__global__ void initA_kernel() {
    int i = blockIdx.x * blockDim.x + threadIdx.x;
    if (i < NN) g_deg_out[i] = 0;
}

__global__ void initB_kernel() {
    int i = blockIdx.x * blockDim.x + threadIdx.x;
    if (i < NN) { g_deg_in[i] = 0; g_fill[i] = 0; }
}

__global__ void countA_kernel(const void* __restrict__ src) {
    int e = blockIdx.x * blockDim.x + threadIdx.x;
    int is64 = g_is64;
    if (e < NE) atomicAdd(&g_deg_out[load_idx(src, e, is64)], 1);
}

__global__ void countB_kernel(const void* __restrict__ dst) {
    int e = blockIdx.x * blockDim.x + threadIdx.x;
    int is64 = g_is64;
    if (e < NE) atomicAdd(&g_deg_in[load_idx(dst, e, is64)], 1);
}

__global__ void normout_kernel() {
    int i = blockIdx.x * blockDim.x + threadIdx.x;
    if (i < NN) g_norm_out[i] = rsqrtf((float)max(g_deg_out[i], 1));
}

__global__ __launch_bounds__(1024) void scanA_kernel() {
    __shared__ int wsum[32];
    int i = blockIdx.x * 1024 + threadIdx.x;
    int lane = threadIdx.x & 31, wid = threadIdx.x >> 5;
    int v = (i < NN) ? g_deg_in[i] : 0;
    int x = v;
    #pragma unroll
    for (int o = 1; o < 32; o <<= 1) {
        int t = __shfl_up_sync(0xffffffffu, x, o);
        if (lane >= o) x += t;
    }
    if (lane == 31) wsum[wid] = x;
    __syncthreads();
    if (wid == 0) {
        int y = wsum[lane];
        #pragma unroll
        for (int o = 1; o < 32; o <<= 1) {
            int t = __shfl_up_sync(0xffffffffu, y, o);
            if (lane >= o) y += t;
        }
        wsum[lane] = y;
    }
    __syncthreads();
    int excl = x - v + (wid > 0 ? wsum[wid - 1] : 0);
    if (i < NN) g_rowptr[i] = excl;
    if (threadIdx.x == 1023) g_bsum[blockIdx.x] = excl + v;
}

__global__ void scanB_kernel() {
    if (threadIdx.x == 0) {
        int s = 0;
        for (int b = 0; b < SCAN_BLK; ++b) {
            int t = g_bsum[b];
            g_bsum[b] = s;
            s += t;
        }
        g_rowptr[NN] = s;
    }
}

__global__ void scanC_kernel() {
    int i = blockIdx.x * blockDim.x + threadIdx.x;
    if (i < NN) {
        g_rowptr[i] += g_bsum[i >> 10];
        g_norm_in[i] = rsqrtf((float)max(g_deg_in[i], 1));
    }
}

__global__ void fill_kernel(const void* __restrict__ src,
                            const void* __restrict__ dst) {
    int e = blockIdx.x * blockDim.x + threadIdx.x;
    int is64 = g_is64;
    if (e < NE) {
        int d = load_idx(dst, e, is64);
        int p = g_rowptr[d] + atomicAdd(&g_fill[d], 1);
        g_col[p] = load_idx(src, e, is64);
    }
}

// ---------------- fp16 MMA helper ----------------
__device__ __forceinline__ void mma_f16(float* c, const unsigned* a, const unsigned* b) {
    asm volatile(
        "mma.sync.aligned.m16n8k16.row.col.f32.f16.f16.f32 "
        "{%0,%1,%2,%3}, {%4,%5,%6,%7}, {%8,%9}, {%0,%1,%2,%3};\n"
        : "+f"(c[0]), "+f"(c[1]), "+f"(c[2]), "+f"(c[3])
        : "r"(a[0]), "r"(a[1]), "r"(a[2]), "r"(a[3]), "r"(b[0]), "r"(b[1]));
}

// ---------------- HMMA GEMM: g_T(half) = (A @ W) * norm_out[:,None] -----------
template <int BN, int SRCSEL>
__global__ __launch_bounds__(256) void gemm_hmma_kernel(const float* __restrict__ Xext,
                                                        const float* __restrict__ W) {
    constexpr int BK = 32, LD = 40;
    constexpr int WARPS_N = BN / 32;
    constexpr int WM = 128 / (8 / WARPS_N);
    constexpr int MFR = WM / 16;
    constexpr int NFR = 4;

    __shared__ __align__(16) __half As[128][LD];
    __shared__ __align__(16) __half Bs[BN][LD];

    const int tid = threadIdx.x;
    const int w = tid >> 5, lane = tid & 31;
    const int gid = lane >> 2, tig = lane & 3;
    const int warp_n = (w % WARPS_N) * 32;
    const int warp_m = (w / WARPS_N) * WM;
    const int m0 = blockIdx.x * 128;

    float acc[MFR][NFR][4];
    #pragma unroll
    for (int a = 0; a < MFR; ++a)
        #pragma unroll
        for (int b = 0; b < NFR; ++b)
            #pragma unroll
            for (int c = 0; c < 4; ++c) acc[a][b][c] = 0.f;

    for (int kc = 0; kc < 128; kc += BK) {
        #pragma unroll
        for (int l = 0; l < 2; ++l) {
            int lin = tid + l * 256;
            int row = lin >> 2;
            int cq  = (lin & 3) * 8;
            int gr  = m0 + row;
            __half2 h[4];
            if (gr < NN) {
                if (SRCSEL == 0) {
                    float4 v1 = *(const float4*)(Xext + gr * 128 + kc + cq);
                    float4 v2 = *(const float4*)(Xext + gr * 128 + kc + cq + 4);
                    h[0] = __floats2half2_rn(v1.x, v1.y);
                    h[1] = __floats2half2_rn(v1.z, v1.w);
                    h[2] = __floats2half2_rn(v2.x, v2.y);
                    h[3] = __floats2half2_rn(v2.z, v2.w);
                } else if (SRCSEL == 1) {
                    uint4 u = *(const uint4*)(g_H1h + gr * 128 + kc + cq);
                    h[0] = *(__half2*)&u.x; h[1] = *(__half2*)&u.y;
                    h[2] = *(__half2*)&u.z; h[3] = *(__half2*)&u.w;
                } else {
                    uint4 u1 = *(const uint4*)(g_H1h + gr * 128 + kc + cq);
                    uint4 u2 = *(const uint4*)(g_H2h + gr * 128 + kc + cq);
                    const unsigned* a1 = &u1.x;
                    const unsigned* a2 = &u2.x;
                    #pragma unroll
                    for (int q = 0; q < 4; ++q) {
                        float2 p = __half22float2(*(__half2*)&a1[q]);
                        float2 r = __half22float2(*(__half2*)&a2[q]);
                        h[q] = __floats2half2_rn(0.9f * p.x + 0.1f * r.x,
                                                 0.9f * p.y + 0.1f * r.y);
                    }
                }
            } else {
                h[0] = h[1] = h[2] = h[3] = __floats2half2_rn(0.f, 0.f);
            }
            uint2 w0, w1;
            w0.x = *(unsigned*)&h[0]; w0.y = *(unsigned*)&h[1];
            w1.x = *(unsigned*)&h[2]; w1.y = *(unsigned*)&h[3];
            *(uint2*)&As[row][cq]     = w0;
            *(uint2*)&As[row][cq + 4] = w1;
        }
        #pragma unroll
        for (int l = 0; l < BN / 32; ++l) {
            int lin = tid + l * 256;
            int k  = lin / (BN / 4);
            int nq = (lin % (BN / 4)) * 4;
            float4 v = *(const float4*)(W + (kc + k) * BN + nq);
            Bs[nq + 0][k] = __float2half_rn(v.x);
            Bs[nq + 1][k] = __float2half_rn(v.y);
            Bs[nq + 2][k] = __float2half_rn(v.z);
            Bs[nq + 3][k] = __float2half_rn(v.w);
        }
        __syncthreads();

        #pragma unroll
        for (int ks = 0; ks < BK; ks += 16) {
            unsigned bh[NFR][2];
            #pragma unroll
            for (int nf = 0; nf < NFR; ++nf) {
                int n = warp_n + nf * 8 + gid;
                bh[nf][0] = *(const unsigned*)&Bs[n][ks + 2 * tig];
                bh[nf][1] = *(const unsigned*)&Bs[n][ks + 2 * tig + 8];
            }
            #pragma unroll
            for (int mf = 0; mf < MFR; ++mf) {
                int m = warp_m + mf * 16;
                unsigned ah[4];
                ah[0] = *(const unsigned*)&As[m + gid][ks + 2 * tig];
                ah[1] = *(const unsigned*)&As[m + gid + 8][ks + 2 * tig];
                ah[2] = *(const unsigned*)&As[m + gid][ks + 2 * tig + 8];
                ah[3] = *(const unsigned*)&As[m + gid + 8][ks + 2 * tig + 8];
                #pragma unroll
                for (int nf = 0; nf < NFR; ++nf)
                    mma_f16(acc[mf][nf], ah, bh[nf]);
            }
        }
        __syncthreads();
    }

    #pragma unroll
    for (int mf = 0; mf < MFR; ++mf) {
        int r0 = m0 + warp_m + mf * 16 + gid;
        int r1 = r0 + 8;
        float no0 = (r0 < NN) ? g_norm_out[r0] : 0.f;
        float no1 = (r1 < NN) ? g_norm_out[r1] : 0.f;
        #pragma unroll
        for (int nf = 0; nf < NFR; ++nf) {
            int col = warp_n + nf * 8 + 2 * tig;
            if (r0 < NN)
                *(__half2*)&g_T[r0 * BN + col] =
                    __floats2half2_rn(acc[mf][nf][0] * no0, acc[mf][nf][1] * no0);
            if (r1 < NN)
                *(__half2*)&g_T[r1 * BN + col] =
                    __floats2half2_rn(acc[mf][nf][2] * no1, acc[mf][nf][3] * no1);
        }
    }
}

// -------- aggregation, F=128: 1 warp/node, 8-deep scalar-unrolled --------
template <bool RELU, int OUTSEL>   // OUTSEL: 0=g_H1h, 1=g_H2h
__global__ __launch_bounds__(256) void agg128_kernel(const float* __restrict__ bias) {
    int w = (blockIdx.x * 256 + threadIdx.x) >> 5;
    int lane = threadIdx.x & 31;
    if (w >= NN) return;
    int s0 = g_rowptr[w];
    int s1 = g_rowptr[w + 1];
    float ni = g_norm_in[w];
    const __half* T = g_T;
    const int off = lane * 4;

    float4 a = make_float4(0.f, 0.f, 0.f, 0.f);
    int e = s0;
    for (; e + 8 <= s1; e += 8) {
        int c0 = g_col[e + 0], c1 = g_col[e + 1];
        int c2 = g_col[e + 2], c3 = g_col[e + 3];
        int c4 = g_col[e + 4], c5 = g_col[e + 5];
        int c6 = g_col[e + 6], c7 = g_col[e + 7];
        uint2 u0 = *(const uint2*)(T + c0 * 128 + off);
        uint2 u1 = *(const uint2*)(T + c1 * 128 + off);
        uint2 u2 = *(const uint2*)(T + c2 * 128 + off);
        uint2 u3 = *(const uint2*)(T + c3 * 128 + off);
        uint2 u4 = *(const uint2*)(T + c4 * 128 + off);
        uint2 u5 = *(const uint2*)(T + c5 * 128 + off);
        uint2 u6 = *(const uint2*)(T + c6 * 128 + off);
        uint2 u7 = *(const uint2*)(T + c7 * 128 + off);
        float2 p, q;
        p = __half22float2(*(__half2*)&u0.x); q = __half22float2(*(__half2*)&u0.y);
        a.x += p.x; a.y += p.y; a.z += q.x; a.w += q.y;
        p = __half22float2(*(__half2*)&u1.x); q = __half22float2(*(__half2*)&u1.y);
        a.x += p.x; a.y += p.y; a.z += q.x; a.w += q.y;
        p = __half22float2(*(__half2*)&u2.x); q = __half22float2(*(__half2*)&u2.y);
        a.x += p.x; a.y += p.y; a.z += q.x; a.w += q.y;
        p = __half22float2(*(__half2*)&u3.x); q = __half22float2(*(__half2*)&u3.y);
        a.x += p.x; a.y += p.y; a.z += q.x; a.w += q.y;
        p = __half22float2(*(__half2*)&u4.x); q = __half22float2(*(__half2*)&u4.y);
        a.x += p.x; a.y += p.y; a.z += q.x; a.w += q.y;
        p = __half22float2(*(__half2*)&u5.x); q = __half22float2(*(__half2*)&u5.y);
        a.x += p.x; a.y += p.y; a.z += q.x; a.w += q.y;
        p = __half22float2(*(__half2*)&u6.x); q = __half22float2(*(__half2*)&u6.y);
        a.x += p.x; a.y += p.y; a.z += q.x; a.w += q.y;
        p = __half22float2(*(__half2*)&u7.x); q = __half22float2(*(__half2*)&u7.y);
        a.x += p.x; a.y += p.y; a.z += q.x; a.w += q.y;
    }
    for (; e + 4 <= s1; e += 4) {
        int c0 = g_col[e + 0], c1 = g_col[e + 1];
        int c2 = g_col[e + 2], c3 = g_col[e + 3];
        uint2 u0 = *(const uint2*)(T + c0 * 128 + off);
        uint2 u1 = *(const uint2*)(T + c1 * 128 + off);
        uint2 u2 = *(const uint2*)(T + c2 * 128 + off);
        uint2 u3 = *(const uint2*)(T + c3 * 128 + off);
        float2 p, q;
        p = __half22float2(*(__half2*)&u0.x); q = __half22float2(*(__half2*)&u0.y);
        a.x += p.x; a.y += p.y; a.z += q.x; a.w += q.y;
        p = __half22float2(*(__half2*)&u1.x); q = __half22float2(*(__half2*)&u1.y);
        a.x += p.x; a.y += p.y; a.z += q.x; a.w += q.y;
        p = __half22float2(*(__half2*)&u2.x); q = __half22float2(*(__half2*)&u2.y);
        a.x += p.x; a.y += p.y; a.z += q.x; a.w += q.y;
        p = __half22float2(*(__half2*)&u3.x); q = __half22float2(*(__half2*)&u3.y);
        a.x += p.x; a.y += p.y; a.z += q.x; a.w += q.y;
    }
    for (; e < s1; ++e) {
        int c = g_col[e];
        uint2 u = *(const uint2*)(T + c * 128 + off);
        float2 p = __half22float2(*(__half2*)&u.x);
        float2 q = __half22float2(*(__half2*)&u.y);
        a.x += p.x; a.y += p.y; a.z += q.x; a.w += q.y;
    }
    float4 b = *(const float4*)(bias + off);
    float4 r = make_float4(fmaf(a.x, ni, b.x), fmaf(a.y, ni, b.y),
                           fmaf(a.z, ni, b.z), fmaf(a.w, ni, b.w));
    if (RELU) {
        r.x = fmaxf(r.x, 0.f); r.y = fmaxf(r.y, 0.f);
        r.z = fmaxf(r.z, 0.f); r.w = fmaxf(r.w, 0.f);
    }
    __half* dstp = (OUTSEL == 0) ? g_H1h : g_H2h;
    uint2 hw;
    __half2 h0 = __floats2half2_rn(r.x, r.y);
    __half2 h1 = __floats2half2_rn(r.z, r.w);
    hw.x = *(unsigned*)&h0; hw.y = *(unsigned*)&h1;
    *(uint2*)(dstp + w * 128 + off) = hw;
}

// -------- aggregation, F=64 (layer 3): 8-deep scalar-unrolled, fp32 out --------
__global__ __launch_bounds__(256) void agg64_kernel(const float* __restrict__ bias,
                                                    float* __restrict__ Oext) {
    int w = (blockIdx.x * 256 + threadIdx.x) >> 5;
    int lane = threadIdx.x & 31;
    if (w >= NN) return;
    int s0 = g_rowptr[w];
    int s1 = g_rowptr[w + 1];
    float ni = g_norm_in[w];
    const __half* T = g_T;
    const int off = lane * 2;

    float2 a = make_float2(0.f, 0.f);
    int e = s0;
    for (; e + 8 <= s1; e += 8) {
        int c0 = g_col[e + 0], c1 = g_col[e + 1];
        int c2 = g_col[e + 2], c3 = g_col[e + 3];
        int c4 = g_col[e + 4], c5 = g_col[e + 5];
        int c6 = g_col[e + 6], c7 = g_col[e + 7];
        unsigned u0 = *(const unsigned*)(T + c0 * 64 + off);
        unsigned u1 = *(const unsigned*)(T + c1 * 64 + off);
        unsigned u2 = *(const unsigned*)(T + c2 * 64 + off);
        unsigned u3 = *(const unsigned*)(T + c3 * 64 + off);
        unsigned u4 = *(const unsigned*)(T + c4 * 64 + off);
        unsigned u5 = *(const unsigned*)(T + c5 * 64 + off);
        unsigned u6 = *(const unsigned*)(T + c6 * 64 + off);
        unsigned u7 = *(const unsigned*)(T + c7 * 64 + off);
        float2 p;
        p = __half22float2(*(__half2*)&u0); a.x += p.x; a.y += p.y;
        p = __half22float2(*(__half2*)&u1); a.x += p.x; a.y += p.y;
        p = __half22float2(*(__half2*)&u2); a.x += p.x; a.y += p.y;
        p = __half22float2(*(__half2*)&u3); a.x += p.x; a.y += p.y;
        p = __half22float2(*(__half2*)&u4); a.x += p.x; a.y += p.y;
        p = __half22float2(*(__half2*)&u5); a.x += p.x; a.y += p.y;
        p = __half22float2(*(__half2*)&u6); a.x += p.x; a.y += p.y;
        p = __half22float2(*(__half2*)&u7); a.x += p.x; a.y += p.y;
    }
    for (; e + 4 <= s1; e += 4) {
        int c0 = g_col[e + 0], c1 = g_col[e + 1];
        int c2 = g_col[e + 2], c3 = g_col[e + 3];
        unsigned u0 = *(const unsigned*)(T + c0 * 64 + off);
        unsigned u1 = *(const unsigned*)(T + c1 * 64 + off);
        unsigned u2 = *(const unsigned*)(T + c2 * 64 + off);
        unsigned u3 = *(const unsigned*)(T + c3 * 64 + off);
        float2 p;
        p = __half22float2(*(__half2*)&u0); a.x += p.x; a.y += p.y;
        p = __half22float2(*(__half2*)&u1); a.x += p.x; a.y += p.y;
        p = __half22float2(*(__half2*)&u2); a.x += p.x; a.y += p.y;
        p = __half22float2(*(__half2*)&u3); a.x += p.x; a.y += p.y;
    }
    for (; e < s1; ++e) {
        int c = g_col[e];
        unsigned u = *(const unsigned*)(T + c * 64 + off);
        float2 p = __half22float2(*(__half2*)&u);
        a.x += p.x; a.y += p.y;
    }
    float2 b = *(const float2*)(bias + off);
    float2 r = make_float2(fmaf(a.x, ni, b.x), fmaf(a.y, ni, b.y));
    *(float2*)(Oext + w * 64 + off) = r;
}

// ---------------- driver (R9/R13 topology) ----------------
extern "C" void kernel_launch(void* const* d_in, const int* in_sizes, int n_in,
                              void* d_out, int out_size) {
    const float* x   = (const float*)d_in[0];
    const void*  src = d_in[1];
    const void*  dst = d_in[2];
    const float* W1 = (const float*)d_in[3];
    const float* b1 = (const float*)d_in[4];
    const float* W2 = (const float*)d_in[5];
    const float* b2 = (const float*)d_in[6];
    const float* W3 = (const float*)d_in[7];
    const float* b3 = (const float*)d_in[8];
    float* out = (float*)d_out;

    const int NB_N = (NN + 255) / 256;
    const int NB_E = (NE + 255) / 256;
    const int NB_G = (NN + 127) / 128;
    const int NB_A = (NN * 32 + 255) / 256;

    static cudaStream_t s1 = nullptr;
    static cudaEvent_t evFork = nullptr, evJoin = nullptr;
    if (s1 == nullptr) {
        cudaStreamCreateWithFlags(&s1, cudaStreamNonBlocking);
        cudaEventCreateWithFlags(&evFork, cudaEventDisableTiming);
        cudaEventCreateWithFlags(&evJoin, cudaEventDisableTiming);
    }

    // --- common root: index dtype detection ---
    detect_kernel<<<1, 32>>>((const int*)src);
    cudaEventRecord(evFork, 0);

    // --- stream s1: dst-side chain (CSR build) ---
    cudaStreamWaitEvent(s1, evFork, 0);
    initB_kernel<<<NB_N, 256, 0, s1>>>();
    countB_kernel<<<NB_E, 256, 0, s1>>>(dst);
    scanA_kernel<<<SCAN_BLK, 1024, 0, s1>>>();
    scanB_kernel<<<1, 32, 0, s1>>>();
    scanC_kernel<<<NB_N, 256, 0, s1>>>();
    fill_kernel<<<NB_E, 256, 0, s1>>>(src, dst);
    cudaEventRecord(evJoin, s1);

    // --- default stream: src-side chain + layer-1 GEMM (overlaps CSR build) ---
    initA_kernel<<<NB_N, 256>>>();
    countA_kernel<<<NB_E, 256>>>(src);
    normout_kernel<<<NB_N, 256>>>();
    gemm_hmma_kernel<128, 0><<<NB_G, 256>>>(x, W1);

    // --- join: aggregation needs CSR + norms ---
    cudaStreamWaitEvent(0, evJoin, 0);
    agg128_kernel<true, 0><<<NB_A, 256>>>(b1);

    // layer 2
    gemm_hmma_kernel<128, 1><<<NB_G, 256>>>(nullptr, W2);
    agg128_kernel<true, 1><<<NB_A, 256>>>(b2);

    // layer 3
    gemm_hmma_kernel<64, 2><<<NB_G, 256>>>(nullptr, W3);
    agg64_kernel<<<NB_A, 256>>>(b3, out);
}

// round 17
// speedup vs baseline: 1.1837x; 1.0065x over previous
#include <cuda_runtime.h>
#include <cuda_fp16.h>

#define NN 100000
#define NE 1600000
#define SCAN_BLK ((NN + 1023) / 1024)   // 98

// ---------------- scratch (static device allocations only) ----------------
__device__ __align__(16) __half g_T[NN * 128];    // fp16 gather payload (normalized)
__device__ __align__(16) __half g_H1h[NN * 128];  // fp16 layer-1 activation
__device__ __align__(16) __half g_H2h[NN * 128];  // fp16 layer-2 activation
__device__ float g_norm_out[NN];
__device__ float g_norm_in[NN];
__device__ int   g_deg_out[NN];
__device__ int   g_deg_in[NN];
__device__ int   g_rowptr[NN + 1];
__device__ int   g_fill[NN];
__device__ int   g_col[NE];
__device__ int   g_bsum[SCAN_BLK];
__device__ int   g_is64;

// ---------------- index dtype detection ----------------
__global__ void detect_kernel(const int* __restrict__ src_raw) {
    if (threadIdx.x == 0 && blockIdx.x == 0) {
        int is64 = 1;
        for (int i = 0; i < 64; ++i)
            if (src_raw[2 * i + 1] != 0) { is64 = 0; break; }
        g_is64 = is64;
    }
}

__device__ __forceinline__ int load_idx(const void* p, int e, int is64) {
    if (is64) return (int)((const long long*)p)[e];
    return ((const int*)p)[e];
}

// ---------------- graph preprocessing ----------------
__global__ void initA_kernel() {
    int i = blockIdx.x * blockDim.x + threadIdx.x;
    if (i < NN) g_deg_out[i] = 0;
}

__global__ void initB_kernel() {
    int i = blockIdx.x * blockDim.x + threadIdx.x;
    if (i < NN) { g_deg_in[i] = 0; g_fill[i] = 0; }
}

__global__ void countA_kernel(const void* __restrict__ src) {
    int e = blockIdx.x * blockDim.x + threadIdx.x;
    int is64 = g_is64;
    if (e < NE) atomicAdd(&g_deg_out[load_idx(src, e, is64)], 1);
}

__global__ void countB_kernel(const void* __restrict__ dst) {
    int e = blockIdx.x * blockDim.x + threadIdx.x;
    int is64 = g_is64;
    if (e < NE) atomicAdd(&g_deg_in[load_idx(dst, e, is64)], 1);
}

__global__ void normout_kernel() {
    int i = blockIdx.x * blockDim.x + threadIdx.x;
    if (i < NN) g_norm_out[i] = rsqrtf((float)max(g_deg_out[i], 1));
}

__global__ __launch_bounds__(1024) void scanA_kernel() {
    __shared__ int wsum[32];
    int i = blockIdx.x * 1024 + threadIdx.x;
    int lane = threadIdx.x & 31, wid = threadIdx.x >> 5;
    int v = (i < NN) ? g_deg_in[i] : 0;
    int x = v;
    #pragma unroll
    for (int o = 1; o < 32; o <<= 1) {
        int t = __shfl_up_sync(0xffffffffu, x, o);
        if (lane >= o) x += t;
    }
    if (lane == 31) wsum[wid] = x;
    __syncthreads();
    if (wid == 0) {
        int y = wsum[lane];
        #pragma unroll
        for (int o = 1; o < 32; o <<= 1) {
            int t = __shfl_up_sync(0xffffffffu, y, o);
            if (lane >= o) y += t;
        }
        wsum[lane] = y;
    }
    __syncthreads();
    int excl = x - v + (wid > 0 ? wsum[wid - 1] : 0);
    if (i < NN) g_rowptr[i] = excl;
    if (threadIdx.x == 1023) g_bsum[blockIdx.x] = excl + v;
}

__global__ void scanB_kernel() {
    if (threadIdx.x == 0) {
        int s = 0;
        for (int b = 0; b < SCAN_BLK; ++b) {
            int t = g_bsum[b];
            g_bsum[b] = s;
            s += t;
        }
        g_rowptr[NN] = s;
    }
}

__global__ void scanC_kernel() {
    int i = blockIdx.x * blockDim.x + threadIdx.x;
    if (i < NN) {
        g_rowptr[i] += g_bsum[i >> 10];
        g_norm_in[i] = rsqrtf((float)max(g_deg_in[i], 1));
    }
}

__global__ void fill_kernel(const void* __restrict__ src,
                            const void* __restrict__ dst) {
    int e = blockIdx.x * blockDim.x + threadIdx.x;
    int is64 = g_is64;
    if (e < NE) {
        int d = load_idx(dst, e, is64);
        int p = g_rowptr[d] + atomicAdd(&g_fill[d], 1);
        g_col[p] = load_idx(src, e, is64);
    }
}

// ---------------- fp16 MMA helper ----------------
__device__ __forceinline__ void mma_f16(float* c, const unsigned* a, const unsigned* b) {
    asm volatile(
        "mma.sync.aligned.m16n8k16.row.col.f32.f16.f16.f32 "
        "{%0,%1,%2,%3}, {%4,%5,%6,%7}, {%8,%9}, {%0,%1,%2,%3};\n"
        : "+f"(c[0]), "+f"(c[1]), "+f"(c[2]), "+f"(c[3])
        : "r"(a[0]), "r"(a[1]), "r"(a[2]), "r"(a[3]), "r"(b[0]), "r"(b[1]));
}

// ---------------- HMMA GEMM, BK=64: g_T(half) = (A @ W) * norm_out[:,None] ----
template <int BN, int SRCSEL>
__global__ __launch_bounds__(256) void gemm_hmma_kernel(const float* __restrict__ Xext,
                                                        const float* __restrict__ W) {
    constexpr int BK = 64, LD = 72;          // 72-half row stride: 36 words ≡ 4 mod 32
    constexpr int WARPS_N = BN / 32;         // 4 (BN=128) or 2 (BN=64)
    constexpr int WM = 128 / (8 / WARPS_N);  // 64 or 32
    constexpr int MFR = WM / 16;             // 4 or 2
    constexpr int NFR = 4;

    __shared__ __align__(16) __half As[128][LD];   // 18 KB
    __shared__ __align__(16) __half Bs[BN][LD];    // 18 KB (BN=128) / 9 KB

    const int tid = threadIdx.x;
    const int w = tid >> 5, lane = tid & 31;
    const int gid = lane >> 2, tig = lane & 3;
    const int warp_n = (w % WARPS_N) * 32;
    const int warp_m = (w / WARPS_N) * WM;
    const int m0 = blockIdx.x * 128;

    float acc[MFR][NFR][4];
    #pragma unroll
    for (int a = 0; a < MFR; ++a)
        #pragma unroll
        for (int b = 0; b < NFR; ++b)
            #pragma unroll
            for (int c = 0; c < 4; ++c) acc[a][b][c] = 0.f;

    for (int kc = 0; kc < 128; kc += BK) {
        // --- A tile: 128 rows x 64 cols -> As[m][k] fp16 (8 halves per thread-iter) ---
        #pragma unroll
        for (int l = 0; l < 4; ++l) {
            int lin = tid + l * 256;
            int row = lin >> 3;              // 8 chunks of 8 halves per 64-col row
            int cq  = (lin & 7) * 8;
            int gr  = m0 + row;
            __half2 h[4];
            if (gr < NN) {
                if (SRCSEL == 0) {
                    float4 v1 = *(const float4*)(Xext + gr * 128 + kc + cq);
                    float4 v2 = *(const float4*)(Xext + gr * 128 + kc + cq + 4);
                    h[0] = __floats2half2_rn(v1.x, v1.y);
                    h[1] = __floats2half2_rn(v1.z, v1.w);
                    h[2] = __floats2half2_rn(v2.x, v2.y);
                    h[3] = __floats2half2_rn(v2.z, v2.w);
                } else if (SRCSEL == 1) {
                    uint4 u = *(const uint4*)(g_H1h + gr * 128 + kc + cq);
                    h[0] = *(__half2*)&u.x; h[1] = *(__half2*)&u.y;
                    h[2] = *(__half2*)&u.z; h[3] = *(__half2*)&u.w;
                } else {
                    uint4 u1 = *(const uint4*)(g_H1h + gr * 128 + kc + cq);
                    uint4 u2 = *(const uint4*)(g_H2h + gr * 128 + kc + cq);
                    const unsigned* a1 = &u1.x;
                    const unsigned* a2 = &u2.x;
                    #pragma unroll
                    for (int q = 0; q < 4; ++q) {
                        float2 p = __half22float2(*(__half2*)&a1[q]);
                        float2 r = __half22float2(*(__half2*)&a2[q]);
                        h[q] = __floats2half2_rn(0.9f * p.x + 0.1f * r.x,
                                                 0.9f * p.y + 0.1f * r.y);
                    }
                }
            } else {
                h[0] = h[1] = h[2] = h[3] = __floats2half2_rn(0.f, 0.f);
            }
            uint2 w0, w1;
            w0.x = *(unsigned*)&h[0]; w0.y = *(unsigned*)&h[1];
            w1.x = *(unsigned*)&h[2]; w1.y = *(unsigned*)&h[3];
            *(uint2*)&As[row][cq]     = w0;
            *(uint2*)&As[row][cq + 4] = w1;
        }
        // --- W tile: 64 x BN fp32 -> transposed Bs[n][k] fp16 ---
        #pragma unroll
        for (int l = 0; l < BN / 16; ++l) {
            int lin = tid + l * 256;
            int k  = lin / (BN / 4);
            int nq = (lin % (BN / 4)) * 4;
            float4 v = *(const float4*)(W + (kc + k) * BN + nq);
            Bs[nq + 0][k] = __float2half_rn(v.x);
            Bs[nq + 1][k] = __float2half_rn(v.y);
            Bs[nq + 2][k] = __float2half_rn(v.z);
            Bs[nq + 3][k] = __float2half_rn(v.w);
        }
        __syncthreads();

        #pragma unroll
        for (int ks = 0; ks < BK; ks += 16) {
            unsigned bh[NFR][2];
            #pragma unroll
            for (int nf = 0; nf < NFR; ++nf) {
                int n = warp_n + nf * 8 + gid;
                bh[nf][0] = *(const unsigned*)&Bs[n][ks + 2 * tig];
                bh[nf][1] = *(const unsigned*)&Bs[n][ks + 2 * tig + 8];
            }
            #pragma unroll
            for (int mf = 0; mf < MFR; ++mf) {
                int m = warp_m + mf * 16;
                unsigned ah[4];
                ah[0] = *(const unsigned*)&As[m + gid][ks + 2 * tig];
                ah[1] = *(const unsigned*)&As[m + gid + 8][ks + 2 * tig];
                ah[2] = *(const unsigned*)&As[m + gid][ks + 2 * tig + 8];
                ah[3] = *(const unsigned*)&As[m + gid + 8][ks + 2 * tig + 8];
                #pragma unroll
                for (int nf = 0; nf < NFR; ++nf)
                    mma_f16(acc[mf][nf], ah, bh[nf]);
            }
        }
        __syncthreads();
    }

    #pragma unroll
    for (int mf = 0; mf < MFR; ++mf) {
        int r0 = m0 + warp_m + mf * 16 + gid;
        int r1 = r0 + 8;
        float no0 = (r0 < NN) ? g_norm_out[r0] : 0.f;
        float no1 = (r1 < NN) ? g_norm_out[r1] : 0.f;
        #pragma unroll
        for (int nf = 0; nf < NFR; ++nf) {
            int col = warp_n + nf * 8 + 2 * tig;
            if (r0 < NN)
                *(__half2*)&g_T[r0 * BN + col] =
                    __floats2half2_rn(acc[mf][nf][0] * no0, acc[mf][nf][1] * no0);
            if (r1 < NN)
                *(__half2*)&g_T[r1 * BN + col] =
                    __floats2half2_rn(acc[mf][nf][2] * no1, acc[mf][nf][3] * no1);
        }
    }
}

// -------- aggregation, F=128: 1 warp/node, 8-deep scalar-unrolled --------
template <bool RELU, int OUTSEL>   // OUTSEL: 0=g_H1h, 1=g_H2h
__global__ __launch_bounds__(256) void agg128_kernel(const float* __restrict__ bias) {
    int w = (blockIdx.x * 256 + threadIdx.x) >> 5;
    int lane = threadIdx.x & 31;
    if (w >= NN) return;
    int s0 = g_rowptr[w];
    int s1 = g_rowptr[w + 1];
    float ni = g_norm_in[w];
    const __half* T = g_T;
    const int off = lane * 4;

    float4 a = make_float4(0.f, 0.f, 0.f, 0.f);
    int e = s0;
    for (; e + 8 <= s1; e += 8) {
        int c0 = g_col[e + 0], c1 = g_col[e + 1];
        int c2 = g_col[e + 2], c3 = g_col[e + 3];
        int c4 = g_col[e + 4], c5 = g_col[e + 5];
        int c6 = g_col[e + 6], c7 = g_col[e + 7];
        uint2 u0 = *(const uint2*)(T + c0 * 128 + off);
        uint2 u1 = *(const uint2*)(T + c1 * 128 + off);
        uint2 u2 = *(const uint2*)(T + c2 * 128 + off);
        uint2 u3 = *(const uint2*)(T + c3 * 128 + off);
        uint2 u4 = *(const uint2*)(T + c4 * 128 + off);
        uint2 u5 = *(const uint2*)(T + c5 * 128 + off);
        uint2 u6 = *(const uint2*)(T + c6 * 128 + off);
        uint2 u7 = *(const uint2*)(T + c7 * 128 + off);
        float2 p, q;
        p = __half22float2(*(__half2*)&u0.x); q = __half22float2(*(__half2*)&u0.y);
        a.x += p.x; a.y += p.y; a.z += q.x; a.w += q.y;
        p = __half22float2(*(__half2*)&u1.x); q = __half22float2(*(__half2*)&u1.y);
        a.x += p.x; a.y += p.y; a.z += q.x; a.w += q.y;
        p = __half22float2(*(__half2*)&u2.x); q = __half22float2(*(__half2*)&u2.y);
        a.x += p.x; a.y += p.y; a.z += q.x; a.w += q.y;
        p = __half22float2(*(__half2*)&u3.x); q = __half22float2(*(__half2*)&u3.y);
        a.x += p.x; a.y += p.y; a.z += q.x; a.w += q.y;
        p = __half22float2(*(__half2*)&u4.x); q = __half22float2(*(__half2*)&u4.y);
        a.x += p.x; a.y += p.y; a.z += q.x; a.w += q.y;
        p = __half22float2(*(__half2*)&u5.x); q = __half22float2(*(__half2*)&u5.y);
        a.x += p.x; a.y += p.y; a.z += q.x; a.w += q.y;
        p = __half22float2(*(__half2*)&u6.x); q = __half22float2(*(__half2*)&u6.y);
        a.x += p.x; a.y += p.y; a.z += q.x; a.w += q.y;
        p = __half22float2(*(__half2*)&u7.x); q = __half22float2(*(__half2*)&u7.y);
        a.x += p.x; a.y += p.y; a.z += q.x; a.w += q.y;
    }
    for (; e + 4 <= s1; e += 4) {
        int c0 = g_col[e + 0], c1 = g_col[e + 1];
        int c2 = g_col[e + 2], c3 = g_col[e + 3];
        uint2 u0 = *(const uint2*)(T + c0 * 128 + off);
        uint2 u1 = *(const uint2*)(T + c1 * 128 + off);
        uint2 u2 = *(const uint2*)(T + c2 * 128 + off);
        uint2 u3 = *(const uint2*)(T + c3 * 128 + off);
        float2 p, q;
        p = __half22float2(*(__half2*)&u0.x); q = __half22float2(*(__half2*)&u0.y);
        a.x += p.x; a.y += p.y; a.z += q.x; a.w += q.y;
        p = __half22float2(*(__half2*)&u1.x); q = __half22float2(*(__half2*)&u1.y);
        a.x += p.x; a.y += p.y; a.z += q.x; a.w += q.y;
        p = __half22float2(*(__half2*)&u2.x); q = __half22float2(*(__half2*)&u2.y);
        a.x += p.x; a.y += p.y; a.z += q.x; a.w += q.y;
        p = __half22float2(*(__half2*)&u3.x); q = __half22float2(*(__half2*)&u3.y);
        a.x += p.x; a.y += p.y; a.z += q.x; a.w += q.y;
    }
    for (; e < s1; ++e) {
        int c = g_col[e];
        uint2 u = *(const uint2*)(T + c * 128 + off);
        float2 p = __half22float2(*(__half2*)&u.x);
        float2 q = __half22float2(*(__half2*)&u.y);
        a.x += p.x; a.y += p.y; a.z += q.x; a.w += q.y;
    }
    float4 b = *(const float4*)(bias + off);
    float4 r = make_float4(fmaf(a.x, ni, b.x), fmaf(a.y, ni, b.y),
                           fmaf(a.z, ni, b.z), fmaf(a.w, ni, b.w));
    if (RELU) {
        r.x = fmaxf(r.x, 0.f); r.y = fmaxf(r.y, 0.f);
        r.z = fmaxf(r.z, 0.f); r.w = fmaxf(r.w, 0.f);
    }
    __half* dstp = (OUTSEL == 0) ? g_H1h : g_H2h;
    uint2 hw;
    __half2 h0 = __floats2half2_rn(r.x, r.y);
    __half2 h1 = __floats2half2_rn(r.z, r.w);
    hw.x = *(unsigned*)&h0; hw.y = *(unsigned*)&h1;
    *(uint2*)(dstp + w * 128 + off) = hw;
}

// -------- aggregation, F=64 (layer 3): 8-deep scalar-unrolled, fp32 out --------
__global__ __launch_bounds__(256) void agg64_kernel(const float* __restrict__ bias,
                                                    float* __restrict__ Oext) {
    int w = (blockIdx.x * 256 + threadIdx.x) >> 5;
    int lane = threadIdx.x & 31;
    if (w >= NN) return;
    int s0 = g_rowptr[w];
    int s1 = g_rowptr[w + 1];
    float ni = g_norm_in[w];
    const __half* T = g_T;
    const int off = lane * 2;

    float2 a = make_float2(0.f, 0.f);
    int e = s0;
    for (; e + 8 <= s1; e += 8) {
        int c0 = g_col[e + 0], c1 = g_col[e + 1];
        int c2 = g_col[e + 2], c3 = g_col[e + 3];
        int c4 = g_col[e + 4], c5 = g_col[e + 5];
        int c6 = g_col[e + 6], c7 = g_col[e + 7];
        unsigned u0 = *(const unsigned*)(T + c0 * 64 + off);
        unsigned u1 = *(const unsigned*)(T + c1 * 64 + off);
        unsigned u2 = *(const unsigned*)(T + c2 * 64 + off);
        unsigned u3 = *(const unsigned*)(T + c3 * 64 + off);
        unsigned u4 = *(const unsigned*)(T + c4 * 64 + off);
        unsigned u5 = *(const unsigned*)(T + c5 * 64 + off);
        unsigned u6 = *(const unsigned*)(T + c6 * 64 + off);
        unsigned u7 = *(const unsigned*)(T + c7 * 64 + off);
        float2 p;
        p = __half22float2(*(__half2*)&u0); a.x += p.x; a.y += p.y;
        p = __half22float2(*(__half2*)&u1); a.x += p.x; a.y += p.y;
        p = __half22float2(*(__half2*)&u2); a.x += p.x; a.y += p.y;
        p = __half22float2(*(__half2*)&u3); a.x += p.x; a.y += p.y;
        p = __half22float2(*(__half2*)&u4); a.x += p.x; a.y += p.y;
        p = __half22float2(*(__half2*)&u5); a.x += p.x; a.y += p.y;
        p = __half22float2(*(__half2*)&u6); a.x += p.x; a.y += p.y;
        p = __half22float2(*(__half2*)&u7); a.x += p.x; a.y += p.y;
    }
    for (; e + 4 <= s1; e += 4) {
        int c0 = g_col[e + 0], c1 = g_col[e + 1];
        int c2 = g_col[e + 2], c3 = g_col[e + 3];
        unsigned u0 = *(const unsigned*)(T + c0 * 64 + off);
        unsigned u1 = *(const unsigned*)(T + c1 * 64 + off);
        unsigned u2 = *(const unsigned*)(T + c2 * 64 + off);
        unsigned u3 = *(const unsigned*)(T + c3 * 64 + off);
        float2 p;
        p = __half22float2(*(__half2*)&u0); a.x += p.x; a.y += p.y;
        p = __half22float2(*(__half2*)&u1); a.x += p.x; a.y += p.y;
        p = __half22float2(*(__half2*)&u2); a.x += p.x; a.y += p.y;
        p = __half22float2(*(__half2*)&u3); a.x += p.x; a.y += p.y;
    }
    for (; e < s1; ++e) {
        int c = g_col[e];
        unsigned u = *(const unsigned*)(T + c * 64 + off);
        float2 p = __half22float2(*(__half2*)&u);
        a.x += p.x; a.y += p.y;
    }
    float2 b = *(const float2*)(bias + off);
    float2 r = make_float2(fmaf(a.x, ni, b.x), fmaf(a.y, ni, b.y));
    *(float2*)(Oext + w * 64 + off) = r;
}

// ---------------- driver (R9/R13 topology) ----------------
extern "C" void kernel_launch(void* const* d_in, const int* in_sizes, int n_in,
                              void* d_out, int out_size) {
    const float* x   = (const float*)d_in[0];
    const void*  src = d_in[1];
    const void*  dst = d_in[2];
    const float* W1 = (const float*)d_in[3];
    const float* b1 = (const float*)d_in[4];
    const float* W2 = (const float*)d_in[5];
    const float* b2 = (const float*)d_in[6];
    const float* W3 = (const float*)d_in[7];
    const float* b3 = (const float*)d_in[8];
    float* out = (float*)d_out;

    const int NB_N = (NN + 255) / 256;
    const int NB_E = (NE + 255) / 256;
    const int NB_G = (NN + 127) / 128;
    const int NB_A = (NN * 32 + 255) / 256;

    static cudaStream_t s1 = nullptr;
    static cudaEvent_t evFork = nullptr, evJoin = nullptr;
    if (s1 == nullptr) {
        cudaStreamCreateWithFlags(&s1, cudaStreamNonBlocking);
        cudaEventCreateWithFlags(&evFork, cudaEventDisableTiming);
        cudaEventCreateWithFlags(&evJoin, cudaEventDisableTiming);
    }

    // --- common root: index dtype detection ---
    detect_kernel<<<1, 32>>>((const int*)src);
    cudaEventRecord(evFork, 0);

    // --- stream s1: dst-side chain (CSR build) ---
    cudaStreamWaitEvent(s1, evFork, 0);
    initB_kernel<<<NB_N, 256, 0, s1>>>();
    countB_kernel<<<NB_E, 256, 0, s1>>>(dst);
    scanA_kernel<<<SCAN_BLK, 1024, 0, s1>>>();
    scanB_kernel<<<1, 32, 0, s1>>>();
    scanC_kernel<<<NB_N, 256, 0, s1>>>();
    fill_kernel<<<NB_E, 256, 0, s1>>>(src, dst);
    cudaEventRecord(evJoin, s1);

    // --- default stream: src-side chain + layer-1 GEMM (overlaps CSR build) ---
    initA_kernel<<<NB_N, 256>>>();
    countA_kernel<<<NB_E, 256>>>(src);
    normout_kernel<<<NB_N, 256>>>();
    gemm_hmma_kernel<128, 0><<<NB_G, 256>>>(x, W1);

    // --- join: aggregation needs CSR + norms ---
    cudaStreamWaitEvent(0, evJoin, 0);
    agg128_kernel<true, 0><<<NB_A, 256>>>(b1);

    // layer 2
    gemm_hmma_kernel<128, 1><<<NB_G, 256>>>(nullptr, W2);
    agg128_kernel<true, 1><<<NB_A, 256>>>(b2);

    // layer 3
    gemm_hmma_kernel<64, 2><<<NB_G, 256>>>(nullptr, W3);
    agg64_kernel<<<NB_A, 256>>>(b3, out);
}